// round 3
// baseline (speedup 1.0000x reference)
#include <cuda_runtime.h>
#include <math.h>

#define Bq 2
#define NEGq 16
#define Nn 10000
#define Ee 80000
#define Dd 128
#define NUMREL 237
#define Lq 3
#define Kq 1000
#define BNq (Bq*Nn)
#define BEq (Bq*Ee)
#define EPSq 1e-5f

// ----------------- persistent device scratch (no allocations) -----------------
__device__ float g_hidden[BNq*Dd];
__device__ float g_score[BNq];
__device__ unsigned char g_sel[BNq];
__device__ int   g_outdeg[BNq];
__device__ float g_s1[BNq*Dd];
__device__ float g_s2[BNq*Dd];
__device__ unsigned int g_mx[BNq*Dd];
__device__ unsigned int g_mn[BNq*Dd];
__device__ int   g_cnt[BNq];
__device__ int   g_asrc[BEq];
__device__ int   g_adst[BEq];
__device__ int   g_gated[BNq];
__device__ int   g_touchedlist[BNq];
__device__ unsigned char g_touched[BNq];
__device__ float g_rel[Bq*Dd];
__device__ float g_hvals[Bq*Dd];
__device__ float g_tvals[Bq*Dd];
__device__ int   g_flat_h[Bq];
__device__ int   g_flat_t[Bq];
__device__ int   g_tgather[Bq*NEGq];
__device__ int   g_nactive;
__device__ int   g_ngated;
__device__ int   g_ntouched;
__device__ float g_avglog_sum;
__device__ float g_c0;

// orderable-uint encoding for float atomic max/min
__device__ __forceinline__ unsigned fenc(float f){
    unsigned u = __float_as_uint(f);
    return (u & 0x80000000u) ? ~u : (u | 0x80000000u);
}
__device__ __forceinline__ float fdec(unsigned e){
    unsigned u = (e & 0x80000000u) ? (e & 0x7fffffffu) : ~e;
    return __uint_as_float(u);
}

// ----------------- setup: tail-swap, flat indices, quirky gathers, c0 -----------------
__global__ void k_setup(const int* h_index, const int* r_index, const int* t_index,
                        const float* hidden_states, const float* rel_embedding,
                        const float* m1_b, const float* m2_W, const float* m2_b){
    __shared__ int sh_h0[Bq], sh_t0[Bq], sh_r0[Bq], sh_neg[Bq];
    int tid = threadIdx.x;
    if (tid < Bq){
        int b = tid;
        int h0 = h_index[b*NEGq];
        int neg = 1;
        for (int j=1;j<NEGq;j++) if (h_index[b*NEGq+j]!=h0) neg=0;
        int hh = neg ? h0 : t_index[b*NEGq];
        int tt = neg ? t_index[b*NEGq] : h0;
        int rr = neg ? r_index[b*NEGq] : r_index[b*NEGq] + NUMREL;
        sh_h0[b]=hh; sh_t0[b]=tt; sh_r0[b]=rr; sh_neg[b]=neg;
        g_flat_h[b] = hh + b*Nn;
        g_flat_t[b] = tt + b*Nn;
    }
    if (tid==0){ g_ntouched = 0; }
    __syncthreads();
    for (int idx=tid; idx<Bq*NEGq; idx+=blockDim.x){
        int b = idx/NEGq;
        int tv = sh_neg[b] ? t_index[idx] : h_index[idx];
        g_tgather[idx] = tv + b*Nn;
    }
    for (int idx=tid; idx<Bq*Dd; idx+=blockDim.x){
        int b = idx/Dd; int d = idx - b*Dd;
        g_rel[idx] = rel_embedding[sh_r0[b]*Dd + d];
        int selb = b / Nn;   // literal repeat_interleave(N)[:B] quirk -> 0
        g_hvals[idx] = hidden_states[sh_h0[selb]*Dd + d];
        g_tvals[idx] = hidden_states[sh_t0[selb]*Dd + d];
    }
    if (tid==0){
        // score of an exactly-zero hidden row: relu(m1_b) @ m2_W + m2_b
        float acc = 0.f;
        for (int d=0; d<Dd; d++){ float h = fmaxf(m1_b[d],0.f); acc += h*m2_W[d]; }
        g_c0 = acc + m2_b[0];
    }
}

__global__ void k_clear_state(){
    int gid = blockIdx.x*blockDim.x + threadIdx.x;
    int stride = gridDim.x*blockDim.x;
    for (int i=gid; i<BNq*Dd; i+=stride) g_hidden[i] = 0.f;
    for (int i=gid; i<BNq; i+=stride){ g_score[i]=0.f; g_touched[i]=0; }
}

__global__ void k_boundary(){
    int b = blockIdx.x, d = threadIdx.x;
    int fh = g_flat_h[b], ft = g_flat_t[b];
    if (ft != fh) g_hidden[ft*Dd + d] = g_tvals[b*Dd + d];
    g_hidden[fh*Dd + d] = g_hvals[b*Dd + d];
    if (d==0){
        int p = atomicAdd(&g_ntouched,1); g_touchedlist[p]=fh; g_touched[fh]=1;
        if (ft != fh){ p = atomicAdd(&g_ntouched,1); g_touchedlist[p]=ft; g_touched[ft]=1; }
    }
}

__global__ void k_init_score(const float* linW, const float* linb,
                             const float* m1W, const float* m1b,
                             const float* m2W, const float* m2b){
    __shared__ float shv[Dd], srl[Dd], sx[Dd], sp[Dd];
    int b = blockIdx.x, d = threadIdx.x;
    shv[d] = g_hvals[b*Dd + d];
    srl[d] = g_rel[b*Dd + d];
    __syncthreads();
    float acc = linb[d];
    for (int k=0;k<Dd;k++) acc += shv[k]*linW[k*Dd + d];
    for (int k=0;k<Dd;k++) acc += srl[k]*linW[(Dd+k)*Dd + d];
    sx[d] = acc * shv[d];
    __syncthreads();
    float h = m1b[d];
    for (int k=0;k<Dd;k++) h += sx[k]*m1W[k*Dd + d];
    h = fmaxf(h, 0.f);
    sp[d] = h * m2W[d];
    __syncthreads();
    if (d==0){
        float s=0.f; for (int k=0;k<Dd;k++) s += sp[k];
        g_score[g_flat_h[b]] = s + m2b[0];
    }
}

__global__ void k_reset_layer(){
    if (threadIdx.x==0 && blockIdx.x==0){ g_nactive=0; g_ngated=0; g_avglog_sum=0.f; }
}

// exact top-K selection with jax.lax.top_k tie semantics (lower index wins)
__global__ void k_rank(){
    __shared__ float ss[Nn];
    const int CH = (Nn + 255)/256;
    int batch = blockIdx.x / CH;
    int chunk = blockIdx.x - batch*CH;
    for (int j=threadIdx.x; j<Nn; j+=blockDim.x) ss[j] = g_score[batch*Nn + j];
    __syncthreads();
    int i = chunk*256 + threadIdx.x;
    if (i < Nn){
        float si = ss[i];
        int rank = 0;
        #pragma unroll 4
        for (int j=0;j<Nn;j++){
            float sj = ss[j];
            rank += (sj > si) || (sj == si && j < i);
        }
        g_sel[batch*Nn + i] = (rank < Kq) ? 1 : 0;
    }
}

__global__ void k_clear_agg(){
    int gid = blockIdx.x*blockDim.x + threadIdx.x;
    int stride = gridDim.x*blockDim.x;
    for (int i=gid; i<BNq*Dd; i+=stride){
        g_s1[i]=0.f; g_s2[i]=0.f; g_mx[i]=0u; g_mn[i]=0xFFFFFFFFu;
    }
    for (int i=gid; i<BNq; i+=stride){ g_cnt[i]=0; g_outdeg[i]=0; }
}

__global__ void k_edge_select(const int* edge_index){
    int gid = blockIdx.x*blockDim.x + threadIdx.x;
    int stride = gridDim.x*blockDim.x;
    for (int e=gid; e<BEq; e+=stride){
        int b = e / Ee;
        int ei = e - b*Ee;
        int s = edge_index[ei] + b*Nn;
        if (g_sel[s]){
            int t = edge_index[Ee + ei] + b*Nn;
            int p = atomicAdd(&g_nactive, 1);
            g_asrc[p] = s; g_adst[p] = t;
            atomicAdd(&g_outdeg[s], 1);
        }
    }
}

__global__ void k_deg(){
    int gid = blockIdx.x*blockDim.x + threadIdx.x;
    float v = 0.f;
    if (gid < BNq){
        int d = g_outdeg[gid];
        int dc = d < 1 ? 1 : d;
        v = logf((float)dc + 1.f);
        if (d > 0){
            int p = atomicAdd(&g_ngated,1); g_gated[p] = gid;
            if (g_touched[gid]==0){
                g_touched[gid]=1;
                int q = atomicAdd(&g_ntouched,1); g_touchedlist[q]=gid;
            }
        }
    }
    for (int o=16;o>0;o>>=1) v += __shfl_down_sync(0xffffffffu, v, o);
    if ((threadIdx.x & 31)==0) atomicAdd(&g_avglog_sum, v);
}

// per-active-edge message (concat-GEMV) fused with atomic aggregation at dst
__global__ void k_message(const float* __restrict__ preW, const float* __restrict__ preb){
    __shared__ float shd[4][Dd], shs[4][Dd];
    __shared__ int sdst[4];
    int tid = threadIdx.x;
    int nact = g_nactive;
    for (int base = blockIdx.x*4; base < nact; base += gridDim.x*4){
        int nv = nact - base; if (nv > 4) nv = 4;
        if (tid < nv){ sdst[tid] = g_adst[base+tid]; }
        __syncthreads();
        for (int j=0;j<nv;j++){
            shd[j][tid] = g_hidden[sdst[j]*Dd + tid];
            shs[j][tid] = g_hidden[g_asrc[base+j]*Dd + tid];
        }
        __syncthreads();
        float pb = preb[tid];
        float a0=pb, a1=pb, a2=pb, a3=pb;
        for (int k=0;k<Dd;k++){
            float w = preW[k*Dd + tid];
            a0 += shd[0][k]*w; a1 += shd[1][k]*w; a2 += shd[2][k]*w; a3 += shd[3][k]*w;
        }
        for (int k=0;k<Dd;k++){
            float w = preW[(Dd+k)*Dd + tid];
            a0 += shs[0][k]*w; a1 += shs[1][k]*w; a2 += shs[2][k]*w; a3 += shs[3][k]*w;
        }
        float av[4] = {a0,a1,a2,a3};
        #pragma unroll
        for (int j=0;j<4;j++){
            if (j < nv){
                float m = av[j];
                int idx = sdst[j]*Dd + tid;
                atomicAdd(&g_s1[idx], m);
                atomicAdd(&g_s2[idx], m*m);
                atomicMax(&g_mx[idx], fenc(m));
                atomicMin(&g_mn[idx], fenc(m));
            }
        }
        if (tid==0){
            for (int j=0;j<nv;j++) atomicAdd(&g_cnt[sdst[j]], 1);
        }
        __syncthreads();
    }
}

// (agg @ postW + postb) @ outW + outb, residual add -- only at gated nodes
__global__ void k_newhidden(const float* __restrict__ postW, const float* __restrict__ postb,
                            const float* __restrict__ outW, const float* __restrict__ outb){
    __shared__ float sagg[4][12*Dd];
    __shared__ float stmp[4][Dd];
    __shared__ int snode[4];
    __shared__ float sf1[4], sf2[4];
    int tid = threadIdx.x;
    int ng = g_ngated;
    float avg = g_avglog_sum / (float)BNq;
    for (int base = blockIdx.x*4; base < ng; base += gridDim.x*4){
        int nv = ng - base; if (nv > 4) nv = 4;
        if (tid < nv){
            int node = g_gated[base+tid];
            snode[tid] = node;
            int dg = g_outdeg[node]; if (dg < 1) dg = 1;
            float logd = logf((float)dg + 1.f);
            sf1[tid] = logd / avg;
            sf2[tid] = avg / logd;
        }
        __syncthreads();
        for (int idx=tid; idx < nv*12*Dd; idx += blockDim.x){
            int n  = idx / (12*Dd);
            int r  = idx - n*(12*Dd);
            int g  = r / Dd;
            int kk = r - g*Dd;
            int c  = g & 3;
            int sg = g >> 2;
            int node = snode[n];
            float cnt = (float)g_cnt[node];
            float denom = fmaxf(cnt, 1.f);
            int ai = node*Dd + kk;
            float v;
            if (c==0)      v = g_s1[ai] / denom;
            else if (c==1) v = (cnt > 0.f) ? fdec(g_mx[ai]) : 0.f;
            else if (c==2) v = (cnt > 0.f) ? fdec(g_mn[ai]) : 0.f;
            else {
                float mean = g_s1[ai] / denom;
                float var  = fmaxf(g_s2[ai]/denom - mean*mean, 0.f);
                v = sqrtf(var + EPSq);
            }
            float f = (sg==0) ? 1.f : ((sg==1) ? sf1[n] : sf2[n]);
            sagg[n][r] = v * f;
        }
        __syncthreads();
        float pb = postb[tid];
        float a0=pb, a1=pb, a2=pb, a3=pb;
        for (int k=0;k<12*Dd;k++){
            float w = postW[k*Dd + tid];
            a0 += sagg[0][k]*w; a1 += sagg[1][k]*w; a2 += sagg[2][k]*w; a3 += sagg[3][k]*w;
        }
        stmp[0][tid]=a0; stmp[1][tid]=a1; stmp[2][tid]=a2; stmp[3][tid]=a3;
        __syncthreads();
        float ob = outb[tid];
        float b0=ob, b1=ob, b2=ob, b3=ob;
        for (int k=0;k<Dd;k++){
            float w = outW[k*Dd + tid];
            b0 += stmp[0][k]*w; b1 += stmp[1][k]*w; b2 += stmp[2][k]*w; b3 += stmp[3][k]*w;
        }
        float bv[4] = {b0,b1,b2,b3};
        #pragma unroll
        for (int j=0;j<4;j++){
            if (j < nv) g_hidden[snode[j]*Dd + tid] += bv[j];
        }
        __syncthreads();
    }
}

__global__ void k_fillscore(){
    int gid = blockIdx.x*blockDim.x + threadIdx.x;
    if (gid < BNq) g_score[gid] = g_c0;
}

// score MLP only over touched (possibly-nonzero hidden) nodes
__global__ void k_score(const float* __restrict__ linW, const float* __restrict__ linb,
                        const float* __restrict__ m1W, const float* __restrict__ m1b,
                        const float* __restrict__ m2W, const float* __restrict__ m2b){
    __shared__ float shid[4][Dd], srel[4][Dd], sx[4][Dd], sp[4][Dd];
    __shared__ int snode[4];
    int tid = threadIdx.x;
    int nt = g_ntouched;
    for (int base = blockIdx.x*4; base < nt; base += gridDim.x*4){
        int nv = nt - base; if (nv > 4) nv = 4;
        if (tid < nv) snode[tid] = g_touchedlist[base+tid];
        __syncthreads();
        for (int j=0;j<nv;j++){
            int node = snode[j];
            shid[j][tid] = g_hidden[node*Dd + tid];
            srel[j][tid] = g_rel[(node/Nn)*Dd + tid];
        }
        __syncthreads();
        float lb = linb[tid];
        float a0=lb, a1=lb, a2=lb, a3=lb;
        for (int k=0;k<Dd;k++){
            float w = linW[k*Dd + tid];
            a0 += shid[0][k]*w; a1 += shid[1][k]*w; a2 += shid[2][k]*w; a3 += shid[3][k]*w;
        }
        for (int k=0;k<Dd;k++){
            float w = linW[(Dd+k)*Dd + tid];
            a0 += srel[0][k]*w; a1 += srel[1][k]*w; a2 += srel[2][k]*w; a3 += srel[3][k]*w;
        }
        sx[0][tid] = a0*shid[0][tid]; sx[1][tid] = a1*shid[1][tid];
        sx[2][tid] = a2*shid[2][tid]; sx[3][tid] = a3*shid[3][tid];
        __syncthreads();
        float mb = m1b[tid];
        float h0=mb, h1=mb, h2=mb, h3=mb;
        for (int k=0;k<Dd;k++){
            float w = m1W[k*Dd + tid];
            h0 += sx[0][k]*w; h1 += sx[1][k]*w; h2 += sx[2][k]*w; h3 += sx[3][k]*w;
        }
        float wm = m2W[tid];
        sp[0][tid] = fmaxf(h0,0.f)*wm; sp[1][tid] = fmaxf(h1,0.f)*wm;
        sp[2][tid] = fmaxf(h2,0.f)*wm; sp[3][tid] = fmaxf(h3,0.f)*wm;
        __syncthreads();
        if (tid < nv){
            float s = 0.f;
            for (int k=0;k<Dd;k++) s += sp[tid][k];
            g_score[snode[tid]] = s + m2b[0];
        }
        __syncthreads();
    }
}

__global__ void k_gather(float* out){
    int idx = threadIdx.x;
    if (idx < Bq*NEGq) out[idx] = g_score[g_tgather[idx]];
}

extern "C" void kernel_launch(void* const* d_in, const int* in_sizes, int n_in,
                              void* d_out, int out_size){
    (void)in_sizes; (void)n_in; (void)out_size;
    const int*   h_index = (const int*)  d_in[0];
    const int*   r_index = (const int*)  d_in[1];
    const int*   t_index = (const int*)  d_in[2];
    const float* hs      = (const float*)d_in[3];
    const int*   eidx    = (const int*)  d_in[4];
    const float* rel     = (const float*)d_in[5];
    const float* linW    = (const float*)d_in[6];
    const float* linb    = (const float*)d_in[7];
    const float* m1W     = (const float*)d_in[8];
    const float* m1b     = (const float*)d_in[9];
    const float* m2W     = (const float*)d_in[10];
    const float* m2b     = (const float*)d_in[11];
    const float* preW    = (const float*)d_in[12];
    const float* preb    = (const float*)d_in[13];
    const float* postW   = (const float*)d_in[14];
    const float* postb   = (const float*)d_in[15];
    const float* outW    = (const float*)d_in[16];
    const float* outb    = (const float*)d_in[17];
    float* out = (float*)d_out;

    k_setup<<<1,256>>>(h_index, r_index, t_index, hs, rel, m1b, m2W, m2b);
    k_clear_state<<<2048,256>>>();
    k_boundary<<<Bq,Dd>>>();
    k_init_score<<<Bq,Dd>>>(linW, linb, m1W, m1b, m2W, m2b);

    for (int l=0; l<Lq; l++){
        k_reset_layer<<<1,32>>>();
        k_rank<<<Bq*((Nn+255)/256),256>>>();
        k_clear_agg<<<2048,256>>>();
        k_edge_select<<<(BEq+255)/256,256>>>(eidx);
        k_deg<<<(BNq+255)/256,256>>>();
        k_message<<<1024,Dd>>>(preW + (size_t)l*2*Dd*Dd, preb + (size_t)l*Dd);
        k_newhidden<<<512,Dd>>>(postW + (size_t)l*12*Dd*Dd, postb + (size_t)l*Dd,
                                outW  + (size_t)l*Dd*Dd,    outb  + (size_t)l*Dd);
        k_fillscore<<<(BNq+255)/256,256>>>();
        k_score<<<512,Dd>>>(linW, linb, m1W, m1b, m2W, m2b);
    }
    k_gather<<<1,32>>>(out);
}

// round 4
// speedup vs baseline: 1.6941x; 1.6941x over previous
#include <cuda_runtime.h>
#include <math.h>

#define Bq 2
#define NEGq 16
#define Nn 10000
#define Ee 80000
#define Dd 128
#define NUMREL 237
#define Lq 3
#define Kq 1000
#define BNq (Bq*Nn)
#define BEq (Bq*Ee)
#define EPSq 1e-5f

// ----------------- persistent device scratch (no allocations) -----------------
__device__ float g_hidden[BNq*Dd];
__device__ float g_score[BNq];
__device__ unsigned char g_sel[BNq];
__device__ int   g_outdeg[BNq];
__device__ int   g_soutdeg[BNq];     // static out-degree (full edge set)
__device__ int   g_indeg[BNq];       // CSR count / fill cursor
__device__ int   g_rowptr[BNq+1];
__device__ int   g_col[BEq];         // CSR-by-dst: src flat ids
__device__ float g_utab[BNq*Dd];     // A·h per touched node (compact)
__device__ float g_vtab[BNq*Dd];     // B·h per touched node (compact)
__device__ int   g_tidx[BNq];        // node -> compact touched index, -1 if untouched
__device__ int   g_gated[BNq];
__device__ int   g_touchedlist[BNq];
__device__ unsigned char g_touched[BNq];
__device__ float g_rel[Bq*Dd];
__device__ float g_hvals[Bq*Dd];
__device__ float g_tvals[Bq*Dd];
__device__ int   g_flat_h[Bq];
__device__ int   g_flat_t[Bq];
__device__ int   g_tgather[Bq*NEGq];
__device__ int   g_ngated;
__device__ int   g_ntouched;
__device__ int   g_ntab;             // touched-count snapshot at table build time
__device__ float g_avglog_sum;
__device__ float g_c0;
__device__ unsigned g_selT[Bq];
__device__ unsigned g_selG[Bq];

// order-preserving encoding for float ranking
__device__ __forceinline__ unsigned fenc(float f){
    unsigned u = __float_as_uint(f);
    return (u & 0x80000000u) ? ~u : (u | 0x80000000u);
}

// ----------------- setup: tail-swap, flat indices, quirky gathers, c0 -----------------
__global__ void k_setup(const int* h_index, const int* r_index, const int* t_index,
                        const float* hidden_states, const float* rel_embedding,
                        const float* m1_b, const float* m2_W, const float* m2_b){
    __shared__ int sh_h0[Bq], sh_t0[Bq], sh_r0[Bq], sh_neg[Bq];
    int tid = threadIdx.x;
    if (tid < Bq){
        int b = tid;
        int h0 = h_index[b*NEGq];
        int neg = 1;
        for (int j=1;j<NEGq;j++) if (h_index[b*NEGq+j]!=h0) neg=0;
        int hh = neg ? h0 : t_index[b*NEGq];
        int tt = neg ? t_index[b*NEGq] : h0;
        int rr = neg ? r_index[b*NEGq] : r_index[b*NEGq] + NUMREL;
        sh_h0[b]=hh; sh_t0[b]=tt; sh_r0[b]=rr; sh_neg[b]=neg;
        g_flat_h[b] = hh + b*Nn;
        g_flat_t[b] = tt + b*Nn;
    }
    if (tid==0){ g_ntouched = 0; }
    __syncthreads();
    for (int idx=tid; idx<Bq*NEGq; idx+=blockDim.x){
        int b = idx/NEGq;
        int tv = sh_neg[b] ? t_index[idx] : h_index[idx];
        g_tgather[idx] = tv + b*Nn;
    }
    for (int idx=tid; idx<Bq*Dd; idx+=blockDim.x){
        int b = idx/Dd; int d = idx - b*Dd;
        g_rel[idx] = rel_embedding[sh_r0[b]*Dd + d];
        int selb = b / Nn;   // literal repeat_interleave(N)[:B] quirk -> 0
        g_hvals[idx] = hidden_states[sh_h0[selb]*Dd + d];
        g_tvals[idx] = hidden_states[sh_t0[selb]*Dd + d];
    }
    if (tid==0){
        // score of an exactly-zero hidden row: relu(m1_b) @ m2_W + m2_b
        float acc = 0.f;
        for (int d=0; d<Dd; d++){ float h = fmaxf(m1_b[d],0.f); acc += h*m2_W[d]; }
        g_c0 = acc + m2_b[0];
    }
}

__global__ void k_clear_state(){
    int gid = blockIdx.x*blockDim.x + threadIdx.x;
    int stride = gridDim.x*blockDim.x;
    for (int i=gid; i<BNq*Dd; i+=stride) g_hidden[i] = 0.f;
    for (int i=gid; i<BNq; i+=stride){
        g_score[i]=0.f; g_touched[i]=0; g_tidx[i]=-1;
        g_indeg[i]=0; g_soutdeg[i]=0;
    }
}

// ----------------- static CSR-by-dst build (edges constant) -----------------
__global__ void k_csr_count(const int* edge_index){
    int gid = blockIdx.x*blockDim.x + threadIdx.x;
    int stride = gridDim.x*blockDim.x;
    for (int e=gid; e<BEq; e+=stride){
        int b = e / Ee; int ei = e - b*Ee;
        int s = edge_index[ei] + b*Nn;
        int d = edge_index[Ee + ei] + b*Nn;
        atomicAdd(&g_indeg[d], 1);
        atomicAdd(&g_soutdeg[s], 1);
    }
}

__global__ void k_csr_scan(){
    __shared__ int wsum[32];
    __shared__ int carry, ctot;
    int tid=threadIdx.x, lane=tid&31, wid=tid>>5;
    if (tid==0) carry=0;
    __syncthreads();
    for (int start=0; start<BNq; start+=1024){
        int i = start + tid;
        int c = (i<BNq) ? g_indeg[i] : 0;
        int inc = c;
        for (int o=1;o<32;o<<=1){ int n=__shfl_up_sync(0xffffffffu,inc,o); if(lane>=o) inc+=n; }
        if (lane==31) wsum[wid]=inc;
        __syncthreads();
        if (wid==0){
            int v=wsum[lane]; int iv=v;
            for (int o=1;o<32;o<<=1){ int n=__shfl_up_sync(0xffffffffu,iv,o); if(lane>=o) iv+=n; }
            wsum[lane]=iv-v;
            if (lane==31) ctot=iv;
        }
        __syncthreads();
        int excl = carry + wsum[wid] + inc - c;
        if (i<BNq){ g_rowptr[i]=excl; g_indeg[i]=excl; }  // reuse g_indeg as fill cursor
        __syncthreads();
        if (tid==0) carry += ctot;
        __syncthreads();
    }
    if (tid==0) g_rowptr[BNq]=carry;
}

__global__ void k_csr_fill(const int* edge_index){
    int gid = blockIdx.x*blockDim.x + threadIdx.x;
    int stride = gridDim.x*blockDim.x;
    for (int e=gid; e<BEq; e+=stride){
        int b = e / Ee; int ei = e - b*Ee;
        int s = edge_index[ei] + b*Nn;
        int d = edge_index[Ee + ei] + b*Nn;
        int pos = atomicAdd(&g_indeg[d], 1);
        g_col[pos] = s;
    }
}

__global__ void k_boundary(){
    int b = blockIdx.x, d = threadIdx.x;
    int fh = g_flat_h[b], ft = g_flat_t[b];
    if (ft != fh) g_hidden[ft*Dd + d] = g_tvals[b*Dd + d];
    g_hidden[fh*Dd + d] = g_hvals[b*Dd + d];
    if (d==0){
        int p = atomicAdd(&g_ntouched,1); g_touchedlist[p]=fh; g_touched[fh]=1; g_tidx[fh]=p;
        if (ft != fh){ p = atomicAdd(&g_ntouched,1); g_touchedlist[p]=ft; g_touched[ft]=1; g_tidx[ft]=p; }
    }
}

__global__ void k_init_score(const float* linW, const float* linb,
                             const float* m1W, const float* m1b,
                             const float* m2W, const float* m2b){
    __shared__ float shv[Dd], srl[Dd], sx[Dd], sp[Dd];
    int b = blockIdx.x, d = threadIdx.x;
    shv[d] = g_hvals[b*Dd + d];
    srl[d] = g_rel[b*Dd + d];
    __syncthreads();
    float acc = linb[d];
    for (int k=0;k<Dd;k++) acc += shv[k]*linW[k*Dd + d];
    for (int k=0;k<Dd;k++) acc += srl[k]*linW[(Dd+k)*Dd + d];
    sx[d] = acc * shv[d];
    __syncthreads();
    float h = m1b[d];
    for (int k=0;k<Dd;k++) h += sx[k]*m1W[k*Dd + d];
    h = fmaxf(h, 0.f);
    sp[d] = h * m2W[d];
    __syncthreads();
    if (d==0){
        float s=0.f; for (int k=0;k<Dd;k++) s += sp[k];
        g_score[g_flat_h[b]] = s + m2b[0];
    }
}

// ----------------- exact top-K threshold via 3-pass histogram radix select -----------------
__global__ void k_select(){
    __shared__ unsigned hist[4096];
    __shared__ unsigned warpSum[32];
    __shared__ unsigned sPrefix, sG;
    int batch = blockIdx.x;
    int tid = threadIdx.x;
    const float* sc = g_score + batch*Nn;
    if (tid==0){ sPrefix=0; sG=0; }
    if (batch==0 && tid==1){ g_ngated=0; g_avglog_sum=0.f; }  // layer reset (consumed after k_mark)
    __syncthreads();
    for (int lvl=0; lvl<3; lvl++){
        for (int i=tid;i<4096;i+=1024) hist[i]=0u;
        __syncthreads();
        unsigned p = sPrefix;
        for (int i=tid;i<Nn;i+=1024){
            unsigned e = fenc(sc[i]);
            unsigned key; bool ok;
            if (lvl==0){ ok=true;            key = e>>20; }
            else if (lvl==1){ ok = (e>>20)==p; key = (e>>8)&0xFFFu; }
            else            { ok = (e>>8)==p;  key = e&0xFFu; }
            if (ok) atomicAdd(&hist[key], 1u);
        }
        __syncthreads();
        unsigned v = hist[tid*4] + hist[tid*4+1] + hist[tid*4+2] + hist[tid*4+3];
        for (int o=16;o>0;o>>=1) v += __shfl_down_sync(0xffffffffu, v, o);
        if ((tid&31)==0) warpSum[tid>>5]=v;
        __syncthreads();
        if (tid==0){
            unsigned R = (unsigned)Kq - sG;
            unsigned acc=0; int beta=0;
            for (int w=31; w>=0; w--){
                if (acc + warpSum[w] >= R){
                    for (int b2 = w*128+127; b2 >= w*128; b2--){
                        if (acc + hist[b2] >= R){ beta=b2; break; }
                        acc += hist[b2];
                    }
                    break;
                }
                acc += warpSum[w];
            }
            sG += acc;
            sPrefix = (lvl==0) ? (unsigned)beta
                    : ((sPrefix << ((lvl==1)?12:8)) | (unsigned)beta);
        }
        __syncthreads();
    }
    if (tid==0){ g_selT[batch]=sPrefix; g_selG[batch]=sG; }
}

// mark sel: all > T, plus first (K-G) ties by ascending index (jax top_k tie order)
__global__ void k_mark(){
    __shared__ int wexcl[32];
    __shared__ int running, chunktot;
    int batch = blockIdx.x;
    int tid = threadIdx.x, lane = tid&31, wid = tid>>5;
    unsigned T = g_selT[batch];
    int R = Kq - (int)g_selG[batch];
    if (tid==0) running=0;
    __syncthreads();
    const float* sc = g_score + batch*Nn;
    for (int start=0; start<Nn; start+=1024){
        int i = start + tid;
        int gt=0, tie=0;
        if (i<Nn){ unsigned e=fenc(sc[i]); gt = (e>T); tie = (e==T); }
        unsigned ball = __ballot_sync(0xffffffffu, tie!=0);
        int lp = __popc(ball & ((lane==0)?0u:((1u<<lane)-1u)));
        int wt = __popc(ball);
        if (lane==0) wexcl[wid]=wt;
        __syncthreads();
        if (wid==0){
            int val = wexcl[lane]; int iv = val;
            for (int o=1;o<32;o<<=1){ int n=__shfl_up_sync(0xffffffffu,iv,o); if(lane>=o) iv+=n; }
            wexcl[lane] = iv - val;
            if (lane==31) chunktot = iv;
        }
        __syncthreads();
        int pref = running + wexcl[wid] + lp;
        if (i<Nn) g_sel[batch*Nn+i] = (gt || (tie && pref < R)) ? 1 : 0;
        __syncthreads();
        if (tid==0) running += chunktot;
        __syncthreads();
    }
}

// u = A·h, v = B·h for all currently-touched nodes (pre-update hidden)
__global__ void k_tables(const float* __restrict__ preW){
    __shared__ float sh[4][Dd];
    __shared__ int sn[4];
    int tid = threadIdx.x;
    int nt = g_ntouched;
    if (blockIdx.x==0 && tid==0) g_ntab = nt;
    for (int base = blockIdx.x*4; base < nt; base += gridDim.x*4){
        int nv = nt - base; if (nv>4) nv=4;
        if (tid < nv) sn[tid] = g_touchedlist[base+tid];
        __syncthreads();
        for (int j=0;j<nv;j++) sh[j][tid] = g_hidden[sn[j]*Dd + tid];
        __syncthreads();
        float u0=0.f,u1=0.f,u2=0.f,u3=0.f;
        float v0=0.f,v1=0.f,v2=0.f,v3=0.f;
        for (int k=0;k<Dd;k++){
            float wa = preW[k*Dd + tid];
            float wb = preW[(Dd+k)*Dd + tid];
            u0 += sh[0][k]*wa; u1 += sh[1][k]*wa; u2 += sh[2][k]*wa; u3 += sh[3][k]*wa;
            v0 += sh[0][k]*wb; v1 += sh[1][k]*wb; v2 += sh[2][k]*wb; v3 += sh[3][k]*wb;
        }
        float uv[4]={u0,u1,u2,u3}, vv[4]={v0,v1,v2,v3};
        #pragma unroll
        for (int j=0;j<4;j++){
            if (j<nv){
                g_utab[(base+j)*Dd + tid] = uv[j];
                g_vtab[(base+j)*Dd + tid] = vv[j];
            }
        }
        __syncthreads();
    }
}

// out_deg = sel ? static_outdeg : 0; gated/touched lists; avglog; score prefill (c0)
__global__ void k_deg(){
    int gid = blockIdx.x*blockDim.x + threadIdx.x;
    float v = 0.f;
    if (gid < BNq){
        int s = g_sel[gid] ? g_soutdeg[gid] : 0;
        g_outdeg[gid] = s;
        g_score[gid] = g_c0;   // prefill; touched rescored by k_score
        int dc = s < 1 ? 1 : s;
        v = logf((float)dc + 1.f);
        if (s > 0){
            int p = atomicAdd(&g_ngated,1); g_gated[p] = gid;
            if (g_touched[gid]==0){
                g_touched[gid]=1;
                int q = atomicAdd(&g_ntouched,1); g_touchedlist[q]=gid; g_tidx[gid]=q;
            }
        }
    }
    for (int o=16;o>0;o>>=1) v += __shfl_down_sync(0xffffffffu, v, o);
    if ((threadIdx.x & 31)==0) atomicAdd(&g_avglog_sum, v);
}

// fused: in-edge aggregation (registers) + scalers + post/out GEMVs + residual
__global__ void k_pna(const float* __restrict__ preb,
                      const float* __restrict__ postW, const float* __restrict__ postb,
                      const float* __restrict__ outW, const float* __restrict__ outb){
    __shared__ float sagg[4][12*Dd];
    __shared__ float stmp[4][Dd];
    __shared__ int snode[4];
    __shared__ float sf1[4], sf2[4];
    int tid = threadIdx.x;
    int ng = g_ngated;
    int ntab = g_ntab;
    float avg = g_avglog_sum / (float)BNq;
    float pb = preb[tid];
    for (int base = blockIdx.x*4; base < ng; base += gridDim.x*4){
        int nv = ng - base; if (nv>4) nv=4;
        if (tid < nv){
            int node = g_gated[base+tid];
            snode[tid] = node;
            int dg = g_outdeg[node]; if (dg<1) dg=1;
            float logd = logf((float)dg + 1.f);
            sf1[tid] = logd/avg; sf2[tid] = avg/logd;
        }
        __syncthreads();
        for (int j=0;j<nv;j++){
            int node = snode[j];
            int ti = g_tidx[node];
            float u = (ti>=0 && ti<ntab) ? g_utab[ti*Dd + tid] : 0.f;
            int rs = g_rowptr[node], re = g_rowptr[node+1];
            float s1=0.f, s2=0.f, mx=-INFINITY, mn=INFINITY;
            int cnt=0;
            for (int e=rs; e<re; e++){
                int s = g_col[e];
                if (g_sel[s]){
                    int vi = g_tidx[s];
                    float vv = (vi>=0 && vi<ntab) ? g_vtab[vi*Dd + tid] : 0.f;
                    float m = pb + u + vv;
                    s1 += m; s2 += m*m;
                    mx = fmaxf(mx, m); mn = fminf(mn, m);
                    cnt++;
                }
            }
            float denom = (cnt>0) ? (float)cnt : 1.f;
            float mean = s1/denom;
            float var  = fmaxf(s2/denom - mean*mean, 0.f);
            float stdv = sqrtf(var + EPSq);
            float mxv = (cnt>0) ? mx : 0.f;
            float mnv = (cnt>0) ? mn : 0.f;
            float f1 = sf1[j], f2 = sf2[j];
            sagg[j][0*Dd+tid]=mean;    sagg[j][1*Dd+tid]=mxv;
            sagg[j][2*Dd+tid]=mnv;     sagg[j][3*Dd+tid]=stdv;
            sagg[j][4*Dd+tid]=mean*f1; sagg[j][5*Dd+tid]=mxv*f1;
            sagg[j][6*Dd+tid]=mnv*f1;  sagg[j][7*Dd+tid]=stdv*f1;
            sagg[j][8*Dd+tid]=mean*f2; sagg[j][9*Dd+tid]=mxv*f2;
            sagg[j][10*Dd+tid]=mnv*f2; sagg[j][11*Dd+tid]=stdv*f2;
        }
        __syncthreads();
        float pob = postb[tid];
        float a0=pob, a1=pob, a2=pob, a3=pob;
        for (int k=0;k<12*Dd;k++){
            float w = postW[k*Dd + tid];
            a0 += sagg[0][k]*w; a1 += sagg[1][k]*w; a2 += sagg[2][k]*w; a3 += sagg[3][k]*w;
        }
        stmp[0][tid]=a0; stmp[1][tid]=a1; stmp[2][tid]=a2; stmp[3][tid]=a3;
        __syncthreads();
        float ob = outb[tid];
        float b0=ob, b1=ob, b2=ob, b3=ob;
        for (int k=0;k<Dd;k++){
            float w = outW[k*Dd + tid];
            b0 += stmp[0][k]*w; b1 += stmp[1][k]*w; b2 += stmp[2][k]*w; b3 += stmp[3][k]*w;
        }
        float bv[4] = {b0,b1,b2,b3};
        #pragma unroll
        for (int j=0;j<4;j++){
            if (j < nv) g_hidden[snode[j]*Dd + tid] += bv[j];
        }
        __syncthreads();
    }
}

// score MLP only over touched (possibly-nonzero hidden) nodes
__global__ void k_score(const float* __restrict__ linW, const float* __restrict__ linb,
                        const float* __restrict__ m1W, const float* __restrict__ m1b,
                        const float* __restrict__ m2W, const float* __restrict__ m2b){
    __shared__ float shid[4][Dd], srel[4][Dd], sx[4][Dd], sp[4][Dd];
    __shared__ int snode[4];
    int tid = threadIdx.x;
    int nt = g_ntouched;
    for (int base = blockIdx.x*4; base < nt; base += gridDim.x*4){
        int nv = nt - base; if (nv > 4) nv = 4;
        if (tid < nv) snode[tid] = g_touchedlist[base+tid];
        __syncthreads();
        for (int j=0;j<nv;j++){
            int node = snode[j];
            shid[j][tid] = g_hidden[node*Dd + tid];
            srel[j][tid] = g_rel[(node/Nn)*Dd + tid];
        }
        __syncthreads();
        float lb = linb[tid];
        float a0=lb, a1=lb, a2=lb, a3=lb;
        for (int k=0;k<Dd;k++){
            float w = linW[k*Dd + tid];
            a0 += shid[0][k]*w; a1 += shid[1][k]*w; a2 += shid[2][k]*w; a3 += shid[3][k]*w;
        }
        for (int k=0;k<Dd;k++){
            float w = linW[(Dd+k)*Dd + tid];
            a0 += srel[0][k]*w; a1 += srel[1][k]*w; a2 += srel[2][k]*w; a3 += srel[3][k]*w;
        }
        sx[0][tid] = a0*shid[0][tid]; sx[1][tid] = a1*shid[1][tid];
        sx[2][tid] = a2*shid[2][tid]; sx[3][tid] = a3*shid[3][tid];
        __syncthreads();
        float mb = m1b[tid];
        float h0=mb, h1=mb, h2=mb, h3=mb;
        for (int k=0;k<Dd;k++){
            float w = m1W[k*Dd + tid];
            h0 += sx[0][k]*w; h1 += sx[1][k]*w; h2 += sx[2][k]*w; h3 += sx[3][k]*w;
        }
        float wm = m2W[tid];
        sp[0][tid] = fmaxf(h0,0.f)*wm; sp[1][tid] = fmaxf(h1,0.f)*wm;
        sp[2][tid] = fmaxf(h2,0.f)*wm; sp[3][tid] = fmaxf(h3,0.f)*wm;
        __syncthreads();
        if (tid < nv){
            float s = 0.f;
            for (int k=0;k<Dd;k++) s += sp[tid][k];
            g_score[snode[tid]] = s + m2b[0];
        }
        __syncthreads();
    }
}

__global__ void k_gather(float* out){
    int idx = threadIdx.x;
    if (idx < Bq*NEGq) out[idx] = g_score[g_tgather[idx]];
}

extern "C" void kernel_launch(void* const* d_in, const int* in_sizes, int n_in,
                              void* d_out, int out_size){
    (void)in_sizes; (void)n_in; (void)out_size;
    const int*   h_index = (const int*)  d_in[0];
    const int*   r_index = (const int*)  d_in[1];
    const int*   t_index = (const int*)  d_in[2];
    const float* hs      = (const float*)d_in[3];
    const int*   eidx    = (const int*)  d_in[4];
    const float* rel     = (const float*)d_in[5];
    const float* linW    = (const float*)d_in[6];
    const float* linb    = (const float*)d_in[7];
    const float* m1W     = (const float*)d_in[8];
    const float* m1b     = (const float*)d_in[9];
    const float* m2W     = (const float*)d_in[10];
    const float* m2b     = (const float*)d_in[11];
    const float* preW    = (const float*)d_in[12];
    const float* preb    = (const float*)d_in[13];
    const float* postW   = (const float*)d_in[14];
    const float* postb   = (const float*)d_in[15];
    const float* outW    = (const float*)d_in[16];
    const float* outb    = (const float*)d_in[17];
    float* out = (float*)d_out;

    k_setup<<<1,256>>>(h_index, r_index, t_index, hs, rel, m1b, m2W, m2b);
    k_clear_state<<<2048,256>>>();
    k_csr_count<<<(BEq+255)/256,256>>>(eidx);
    k_csr_scan<<<1,1024>>>();
    k_csr_fill<<<(BEq+255)/256,256>>>(eidx);
    k_boundary<<<Bq,Dd>>>();
    k_init_score<<<Bq,Dd>>>(linW, linb, m1W, m1b, m2W, m2b);

    for (int l=0; l<Lq; l++){
        k_select<<<Bq,1024>>>();
        k_mark<<<Bq,1024>>>();
        k_tables<<<512,Dd>>>(preW + (size_t)l*2*Dd*Dd);
        k_deg<<<(BNq+255)/256,256>>>();
        k_pna<<<512,Dd>>>(preb + (size_t)l*Dd,
                          postW + (size_t)l*12*Dd*Dd, postb + (size_t)l*Dd,
                          outW  + (size_t)l*Dd*Dd,    outb  + (size_t)l*Dd);
        k_score<<<512,Dd>>>(linW, linb, m1W, m1b, m2W, m2b);
    }
    k_gather<<<1,32>>>(out);
}